// round 15
// baseline (speedup 1.0000x reference)
#include <cuda_runtime.h>
#include <cuda_fp16.h>
#include <cstdint>

#define BATCH 8
#define SEQ   1024
#define DIM   1024
#define NH    16
#define HD    64

// plain fp16 operands
__device__ __half g_x [BATCH*SEQ*DIM];     // x   [m][k]
__device__ __half g_wt[3*DIM*DIM];         // W^T [n][k]

// attention operands (written by QKV GEMM epilogue)
__device__ __half g_q [BATCH*NH*SEQ*HD];   // Q  [bh][s][hd]
__device__ __half g_k [BATCH*NH*SEQ*HD];   // K  [bh][s][hd]
__device__ __half g_vt[BATCH*NH*HD*SEQ];   // V^T [bh][hd][s]

// binary mask packed to u8
__device__ uint8_t g_m8[BATCH*SEQ*SEQ];

// ---------------------------------------------------------------------------
// helpers
// ---------------------------------------------------------------------------
__device__ __forceinline__ uint32_t smem_u32(const void* p) {
    uint32_t a;
    asm("{ .reg .u64 t; cvta.to.shared.u64 t, %1; cvt.u32.u64 %0, t; }"
        : "=r"(a) : "l"(p));
    return a;
}
__device__ __forceinline__ void ldsm_x4(uint32_t a[4], uint32_t addr) {
    asm volatile("ldmatrix.sync.aligned.m8n8.x4.shared.b16 {%0,%1,%2,%3}, [%4];"
                 : "=r"(a[0]), "=r"(a[1]), "=r"(a[2]), "=r"(a[3]) : "r"(addr));
}
__device__ __forceinline__ void mma_f16(float c[4], const uint32_t a[4],
                                        const uint32_t b[2]) {
    asm volatile(
        "mma.sync.aligned.m16n8k16.row.col.f32.f16.f16.f32 "
        "{%0,%1,%2,%3}, {%4,%5,%6,%7}, {%8,%9}, {%0,%1,%2,%3};"
        : "+f"(c[0]), "+f"(c[1]), "+f"(c[2]), "+f"(c[3])
        : "r"(a[0]), "r"(a[1]), "r"(a[2]), "r"(a[3]), "r"(b[0]), "r"(b[1]));
}
__device__ __forceinline__ uint32_t pack_f16(__half a, __half b) {
    __half2 p; p.x = a; p.y = b;
    return *(uint32_t*)&p;
}
// packed {lo, hi} f16x2 from two floats
__device__ __forceinline__ uint32_t cvt_f16x2(float lo, float hi) {
    uint32_t r;
    asm("cvt.rn.f16x2.f32 %0, %1, %2;" : "=r"(r) : "f"(hi), "f"(lo));
    return r;
}
__device__ __forceinline__ void cp16(uint32_t dst, const void* src) {
    asm volatile("cp.async.cg.shared.global [%0], [%1], 16;"
                 :: "r"(dst), "l"(src));
}
#define CP_COMMIT() asm volatile("cp.async.commit_group;" ::: "memory")
#define CP_WAIT(n)  asm volatile("cp.async.wait_group %0;" :: "n"(n) : "memory")

// exp(s/8) via exp2 poly: t = s*log2e/8; magic round; degree-4 on [-.5,.5]
__device__ __forceinline__ float fexp8(float s) {
    float t = s * 0.18033688011112042f;          // log2(e)/8
    float k = t + 12582912.0f;                   // 1.5*2^23 magic round
    float j = k - 12582912.0f;
    float f = t - j;
    float p = 9.6181291076e-3f;
    p = fmaf(p, f, 5.5504108665e-2f);
    p = fmaf(p, f, 2.4022650696e-1f);
    p = fmaf(p, f, 6.9314718056e-1f);
    p = fmaf(p, f, 1.0f);
    int ib = __float_as_int(k) - 0x4B400000;
    float scale = __int_as_float((ib + 127) << 23);
    return p * scale;
}

// ---------------------------------------------------------------------------
// Fused preprocess: blocks [0, 8192) convert x -> fp16;
//                   blocks [8192, 16384) pack mask -> u8.
// ---------------------------------------------------------------------------
#define XBLOCKS 8192
__global__ __launch_bounds__(256) void convert_xm_kernel(
    const float* __restrict__ x, const float* __restrict__ m)
{
    int bid = blockIdx.x;
    if (bid < XBLOCKS) {
        int i = (bid * 256 + threadIdx.x) * 4;
        float4 v = *(const float4*)(x + i);
        *(uint32_t*)(g_x + i)     = pack_f16(__float2half_rn(v.x),
                                             __float2half_rn(v.y));
        *(uint32_t*)(g_x + i + 2) = pack_f16(__float2half_rn(v.z),
                                             __float2half_rn(v.w));
    } else {
        int i = ((bid - XBLOCKS) * 256 + threadIdx.x) * 4;
        float4 v = *(const float4*)(m + i);
        uint32_t p = (uint32_t)(v.x != 0.0f)
                   | ((uint32_t)(v.y != 0.0f) << 8)
                   | ((uint32_t)(v.z != 0.0f) << 16)
                   | ((uint32_t)(v.w != 0.0f) << 24);
        *(uint32_t*)(g_m8 + i) = p;
    }
}

// Preprocess: W[k][n] -> Wt[n][k] fp16
__global__ __launch_bounds__(256) void convert_wt_kernel(
    const float* __restrict__ Wq, const float* __restrict__ Wk,
    const float* __restrict__ Wv)
{
    __shared__ float t[32][33];
    const int z = blockIdx.z;
    const float* __restrict__ W = (z == 0) ? Wq : (z == 1 ? Wk : Wv);
    const int n0 = blockIdx.x * 32, k0 = blockIdx.y * 32;
    const int tx = threadIdx.x, ty = threadIdx.y;   // block (32, 8)

    #pragma unroll
    for (int i = ty; i < 32; i += 8)
        t[i][tx] = W[(size_t)(k0 + i) * DIM + n0 + tx];
    __syncthreads();

    __half* wt = g_wt + (size_t)z * DIM * DIM;
    #pragma unroll
    for (int i = ty; i < 32; i += 8)
        wt[(size_t)(n0 + i) * DIM + k0 + tx] = __float2half_rn(t[tx][i]);
}

// ---------------------------------------------------------------------------
// QKV projection GEMM (unchanged from R13): plain fp16, 1 MMA per tile.
//   CTA tile 64x128, 8 warps (2x4), warp tile 32x32, BK=64, 4 CTAs/SM.
// ---------------------------------------------------------------------------
#define BK 64
#define LDS 72
#define QXREG (64 * LDS)
#define QWOFF (QXREG * 2)
#define QBUFB ((64 + 128) * LDS * 2)
#define QKV_SMEM (2 * QBUFB)

__device__ __forceinline__ void qkv_cp_blk(
    uint32_t dstb, const __half* sx, const __half* sw, int k0, int tid)
{
    const __half* x = sx + k0;
    #pragma unroll
    for (int i = tid; i < 512; i += 256) {
        int r = i >> 3, c8 = (i & 7) * 8;
        cp16(dstb + (r * LDS + c8) * 2, x + (size_t)r * DIM + c8);
    }
    const __half* wsrc = sw + k0;
    #pragma unroll
    for (int i = tid; i < 1024; i += 256) {
        int r = i >> 3, c8 = (i & 7) * 8;
        cp16(dstb + QWOFF + (r * LDS + c8) * 2, wsrc + (size_t)r * DIM + c8);
    }
}

__global__ __launch_bounds__(256, 4) void qkv_mma_kernel()
{
    extern __shared__ __half smd[];
    const uint32_t smb = smem_u32(smd);

    const int tid  = threadIdx.x;
    const int w    = tid >> 5, lane = tid & 31;
    const int wm   = w >> 2, wn = w & 3;
    const int m0   = blockIdx.x * 64;
    const int n0   = blockIdx.y * 128;
    const int z    = blockIdx.z;

    const __half* sx = g_x + (size_t)m0 * DIM;
    const __half* sw = g_wt + (size_t)z * DIM * DIM + (size_t)n0 * DIM;

    const int a_row = lane & 15, a_kh = (lane >> 4) * 8;
    const int b_row = (lane & 7) + ((lane >> 4) << 3);
    const int b_kh  = ((lane >> 3) & 1) * 8;

    float acc[2][4][4] = {};

    qkv_cp_blk(smb, sx, sw, 0, tid); CP_COMMIT();

    const int NB = DIM / BK;   // 16
    for (int blk = 0; blk < NB; blk++) {
        CP_WAIT(0);
        __syncthreads();
        if (blk + 1 < NB) {
            qkv_cp_blk(smb + ((blk + 1) & 1) * QBUFB, sx, sw,
                       (blk + 1) * BK, tid);
            CP_COMMIT();
        }

        const uint32_t bb = smb + (blk & 1) * QBUFB;
        #pragma unroll
        for (int kk = 0; kk < BK; kk += 16) {
            uint32_t ax[2][4];
            #pragma unroll
            for (int mt = 0; mt < 2; mt++) {
                int roff = ((wm * 32 + mt * 16 + a_row) * LDS + kk + a_kh) * 2;
                ldsm_x4(ax[mt], bb + roff);
            }
            uint32_t bw[2][4];
            #pragma unroll
            for (int p = 0; p < 2; p++) {
                int roff = ((wn * 32 + p * 16 + b_row) * LDS + kk + b_kh) * 2;
                ldsm_x4(bw[p], bb + QWOFF + roff);
            }
            #pragma unroll
            for (int mt = 0; mt < 2; mt++)
                #pragma unroll
                for (int p = 0; p < 2; p++) {
                    mma_f16(acc[mt][p * 2],     ax[mt], &bw[p][0]);
                    mma_f16(acc[mt][p * 2 + 1], ax[mt], &bw[p][2]);
                }
        }
    }

    // epilogue -> fp16 (q, k plain row-major; v^T plain)
    const int em = lane >> 2, en = (lane & 3) * 2;
    #pragma unroll
    for (int mt = 0; mt < 2; mt++) {
        #pragma unroll
        for (int nt = 0; nt < 4; nt++) {
            int mg0 = m0 + wm * 32 + mt * 16 + em;
            int ng  = n0 + wn * 32 + nt * 8 + en;
            int h = ng >> 6, hd = ng & 63;
            #pragma unroll
            for (int half_i = 0; half_i < 2; half_i++) {
                int mg = mg0 + half_i * 8;
                int b = mg >> 10, s = mg & 1023;
                int bhI = b * NH + h;
                float c0 = acc[mt][nt][half_i * 2 + 0];
                float c1 = acc[mt][nt][half_i * 2 + 1];
                __half h0 = __float2half_rn(c0);
                __half h1 = __float2half_rn(c1);
                if (z == 2) {
                    size_t base = ((size_t)bhI * HD + hd) * SEQ + s;
                    g_vt[base] = h0; g_vt[base + SEQ] = h1;
                } else {
                    size_t off = ((size_t)bhI * SEQ + s) * HD + hd;
                    *(uint32_t*)((z ? g_k : g_q) + off) = pack_f16(h0, h1);
                }
            }
        }
    }
}

// ---------------------------------------------------------------------------
// Attention (R13 u8-mask version): plain fp16 mma.sync, 1 MMA QK + 1 MMA PV.
//   smem: 2 buffers x { K, V [64][72] fp16 (18432 B) + mask 8 KB } = 53248 B.
//   Q (plain, 18432 B) staged in buffer 0 at startup, then recycled.
// ---------------------------------------------------------------------------
#define ATS 72
#define SM_K  (64 * ATS)             // 4608 elems per region
#define AMASK_OFF (2 * SM_K * 2)     // 18432: mask byte offset within buffer
#define ABUF_BYTES (AMASK_OFF + 8192)  // 26624
#define ATTN_SMEM (2 * ABUF_BYTES)   // 53248

__device__ __forceinline__ void attn_cp_tile(
    uint32_t dstb, const __half* K, const __half* V,
    const uint8_t* M8, int kt, int tid)
{
    #pragma unroll
    for (int i = tid; i < 512; i += 256) {
        int r = i >> 3, c8 = (i & 7) * 8;
        uint32_t d = dstb + (r * ATS + c8) * 2;
        cp16(d,            K + (size_t)(kt * 64 + r) * HD + c8);
        cp16(d + SM_K * 2, V + (size_t)r * SEQ + kt * 64 + c8);
    }
    // mask tile: 128 rows x 64 u8
    #pragma unroll
    for (int i = tid; i < 512; i += 256) {
        int r = i >> 2, c16 = (i & 3) * 16;
        cp16(dstb + AMASK_OFF + r * 64 + c16,
             M8 + (size_t)r * SEQ + kt * 64 + c16);
    }
}

__global__ __launch_bounds__(256, 2) void attn_mma_kernel(float* __restrict__ out)
{
    extern __shared__ __half smd[];
    const uint32_t smb = smem_u32(smd);
    const char* sb = (const char*)smd;

    const int tid = threadIdx.x, w = tid >> 5, lane = tid & 31;
    const int qt = blockIdx.x, bh = blockIdx.y;
    const int b = bh >> 4, h = bh & 15;
    const int gr = lane >> 2, gc2 = (lane & 3) * 2;

    const __half* Q  = g_q  + ((size_t)bh * SEQ + qt * 128) * HD;
    const __half* K  = g_k  + (size_t)bh * SEQ * HD;
    const __half* V  = g_vt + (size_t)bh * HD * SEQ;
    const uint8_t* M8 = g_m8 + (size_t)b * SEQ * SEQ + (size_t)(qt * 128) * SEQ;

    // ---- stage Q (plain) in buffer space, consume to registers ----
    #pragma unroll
    for (int i = tid; i < 1024; i += 256) {
        int r = i >> 3, c8 = (i & 7) * 8;
        cp16(smb + (r * ATS + c8) * 2, Q + (size_t)r * HD + c8);
    }
    CP_COMMIT();
    CP_WAIT(0);
    __syncthreads();

    uint32_t qf[4][4];
    {
        const int ar = w * 16 + (lane & 15);
        const int ac = ((lane >> 4) & 1) * 8;
        #pragma unroll
        for (int ks = 0; ks < 4; ks++)
            ldsm_x4(qf[ks], smb + (ar * ATS + ks * 16 + ac) * 2);
    }
    __syncthreads();   // all warps done reading Q before buffers are recycled

    attn_cp_tile(smb, K, V, M8, 0, tid); CP_COMMIT();

    float ctx[8][4] = {};
    float rs0 = 0.f, rs1 = 0.f;

    const int br = (lane & 7) + ((lane >> 4) << 3);
    const int bc = ((lane >> 3) & 1) * 8;
    const int mrow_off = (w * 16 + gr) * 64 + gc2;

    for (int kt = 0; kt < 16; kt++) {
        CP_WAIT(0);
        __syncthreads();
        if (kt + 1 < 16) {
            attn_cp_tile(smb + ((kt + 1) & 1) * ABUF_BYTES,
                         K, V, M8, kt + 1, tid);
            CP_COMMIT();
        }

        const uint32_t bb = smb + (kt & 1) * ABUF_BYTES;

        // ---- scores = Q K^T (plain: 1 MMA) ----
        float acc[8][4] = {};
        #pragma unroll
        for (int ks = 0; ks < 4; ks++) {
            #pragma unroll
            for (int ntp = 0; ntp < 4; ntp++) {
                uint32_t k4[4];
                int off = ((ntp * 16 + br) * ATS + ks * 16 + bc) * 2;
                ldsm_x4(k4, bb + off);
                mma_f16(acc[ntp * 2],     qf[ks], &k4[0]);
                mma_f16(acc[ntp * 2 + 1], qf[ks], &k4[2]);
            }
        }

        // ---- e = poly_exp(s/8) * mask (u8 from smem); sums; P frags ----
        const char* mp = sb + (kt & 1) * ABUF_BYTES + AMASK_OFF + mrow_off;
        uint32_t ph[4][4];
        #pragma unroll
        for (int nt = 0; nt < 8; nt++) {
            uint32_t mm01 = *(const uint16_t*)(mp + nt * 8);
            uint32_t mm23 = *(const uint16_t*)(mp + 512 + nt * 8);
            float e0 = fexp8(acc[nt][0]) * (float)(mm01 & 0xFF);
            float e1 = fexp8(acc[nt][1]) * (float)(mm01 >> 8);
            float e2 = fexp8(acc[nt][2]) * (float)(mm23 & 0xFF);
            float e3 = fexp8(acc[nt][3]) * (float)(mm23 >> 8);
            rs0 += e0 + e1;
            rs1 += e2 + e3;
            int u = nt >> 1, sel = (nt & 1) * 2;
            ph[u][sel]     = cvt_f16x2(e0, e1);
            ph[u][sel + 1] = cvt_f16x2(e2, e3);
        }

        // ---- ctx += P V (plain: 1 MMA) ----
        #pragma unroll
        for (int u = 0; u < 4; u++) {
            #pragma unroll
            for (int dtp = 0; dtp < 4; dtp++) {
                uint32_t v4[4];
                int off = ((dtp * 16 + br) * ATS + u * 16 + bc) * 2;
                ldsm_x4(v4, bb + SM_K * 2 + off);
                mma_f16(ctx[dtp * 2],     ph[u], &v4[0]);
                mma_f16(ctx[dtp * 2 + 1], ph[u], &v4[2]);
            }
        }
    }

    // ---- denominators + output ----
    rs0 += __shfl_xor_sync(0xffffffffu, rs0, 1);
    rs0 += __shfl_xor_sync(0xffffffffu, rs0, 2);
    rs1 += __shfl_xor_sync(0xffffffffu, rs1, 1);
    rs1 += __shfl_xor_sync(0xffffffffu, rs1, 2);
    float inv0 = 1.0f / (rs0 + 1e-8f);
    float inv1 = 1.0f / (rs1 + 1e-8f);

    const int s0 = qt * 128 + w * 16 + gr;
    float* O = out + (((size_t)b * SEQ + s0) * NH + h) * HD + gc2;
    #pragma unroll
    for (int dt = 0; dt < 8; dt++) {
        *(float2*)&O[dt * 8] =
            make_float2(ctx[dt][0] * inv0, ctx[dt][1] * inv0);
        *(float2*)&O[(size_t)8 * NH * HD + dt * 8] =
            make_float2(ctx[dt][2] * inv1, ctx[dt][3] * inv1);
    }
}

// ---------------------------------------------------------------------------
extern "C" void kernel_launch(void* const* d_in, const int* in_sizes, int n_in,
                              void* d_out, int out_size)
{
    const float* x    = (const float*)d_in[0];
    const float* mask = (const float*)d_in[1];
    const float* Wq   = (const float*)d_in[2];
    const float* Wk   = (const float*)d_in[3];
    const float* Wv   = (const float*)d_in[4];
    float* out = (float*)d_out;

    static int init = 0;
    if (!init) {
        cudaFuncSetAttribute(qkv_mma_kernel,
            cudaFuncAttributeMaxDynamicSharedMemorySize, QKV_SMEM);
        cudaFuncSetAttribute(attn_mma_kernel,
            cudaFuncAttributeMaxDynamicSharedMemorySize, ATTN_SMEM);
        init = 1;
    }

    // x: 8192 blocks; mask u8: 8.4M floats / 1024 per block = 8192 blocks
    convert_xm_kernel<<<XBLOCKS + 8192, 256>>>(x, mask);
    convert_wt_kernel<<<dim3(32, 32, 3), dim3(32, 8)>>>(Wq, Wk, Wv);
    qkv_mma_kernel<<<dim3(128, 8, 3), 256, QKV_SMEM>>>();
    attn_mma_kernel<<<dim3(8, 128), 256, ATTN_SMEM>>>(out);
}

// round 16
// speedup vs baseline: 1.0411x; 1.0411x over previous
#include <cuda_runtime.h>
#include <cuda_fp16.h>
#include <cstdint>

#define BATCH 8
#define SEQ   1024
#define DIM   1024
#define NH    16
#define HD    64

// plain fp16 operands
__device__ __half g_x [BATCH*SEQ*DIM];     // x   [m][k]
__device__ __half g_wt[3*DIM*DIM];         // W^T [n][k]

// attention operands (written by QKV GEMM epilogue)
__device__ __half g_q [BATCH*NH*SEQ*HD];   // Q  [bh][s][hd]
__device__ __half g_k [BATCH*NH*SEQ*HD];   // K  [bh][s][hd]
__device__ __half g_vt[BATCH*NH*HD*SEQ];   // V^T [bh][hd][s]

// binary mask packed to bits: word w of row (b,i) holds cols w*32..w*32+31
__device__ uint32_t g_mb[BATCH*SEQ*(SEQ/32)];

// ---------------------------------------------------------------------------
// helpers
// ---------------------------------------------------------------------------
__device__ __forceinline__ uint32_t smem_u32(const void* p) {
    uint32_t a;
    asm("{ .reg .u64 t; cvta.to.shared.u64 t, %1; cvt.u32.u64 %0, t; }"
        : "=r"(a) : "l"(p));
    return a;
}
__device__ __forceinline__ void ldsm_x4(uint32_t a[4], uint32_t addr) {
    asm volatile("ldmatrix.sync.aligned.m8n8.x4.shared.b16 {%0,%1,%2,%3}, [%4];"
                 : "=r"(a[0]), "=r"(a[1]), "=r"(a[2]), "=r"(a[3]) : "r"(addr));
}
__device__ __forceinline__ void mma_f16(float c[4], const uint32_t a[4],
                                        const uint32_t b[2]) {
    asm volatile(
        "mma.sync.aligned.m16n8k16.row.col.f32.f16.f16.f32 "
        "{%0,%1,%2,%3}, {%4,%5,%6,%7}, {%8,%9}, {%0,%1,%2,%3};"
        : "+f"(c[0]), "+f"(c[1]), "+f"(c[2]), "+f"(c[3])
        : "r"(a[0]), "r"(a[1]), "r"(a[2]), "r"(a[3]), "r"(b[0]), "r"(b[1]));
}
__device__ __forceinline__ uint32_t pack_f16(__half a, __half b) {
    __half2 p; p.x = a; p.y = b;
    return *(uint32_t*)&p;
}
// packed {lo, hi} f16x2 from two floats
__device__ __forceinline__ uint32_t cvt_f16x2(float lo, float hi) {
    uint32_t r;
    asm("cvt.rn.f16x2.f32 %0, %1, %2;" : "=r"(r) : "f"(hi), "f"(lo));
    return r;
}
__device__ __forceinline__ void cp16(uint32_t dst, const void* src) {
    asm volatile("cp.async.cg.shared.global [%0], [%1], 16;"
                 :: "r"(dst), "l"(src));
}
__device__ __forceinline__ void cp8(uint32_t dst, const void* src) {
    asm volatile("cp.async.ca.shared.global [%0], [%1], 8;"
                 :: "r"(dst), "l"(src));
}
#define CP_COMMIT() asm volatile("cp.async.commit_group;" ::: "memory")
#define CP_WAIT(n)  asm volatile("cp.async.wait_group %0;" :: "n"(n) : "memory")

// mask bit -> 1.0f/0.0f without I2F: -bit & 0x3F800000
__device__ __forceinline__ float bit_to_f(uint32_t word, int sh) {
    return __int_as_float((int)(-((word >> sh) & 1u)) & 0x3F800000);
}

// exp(s/8) via exp2 poly: t = s*log2e/8; magic round; degree-4 on [-.5,.5]
__device__ __forceinline__ float fexp8(float s) {
    float t = s * 0.18033688011112042f;          // log2(e)/8
    float k = t + 12582912.0f;                   // 1.5*2^23 magic round
    float j = k - 12582912.0f;
    float f = t - j;
    float p = 9.6181291076e-3f;
    p = fmaf(p, f, 5.5504108665e-2f);
    p = fmaf(p, f, 2.4022650696e-1f);
    p = fmaf(p, f, 6.9314718056e-1f);
    p = fmaf(p, f, 1.0f);
    int ib = __float_as_int(k) - 0x4B400000;
    float scale = __int_as_float((ib + 127) << 23);
    return p * scale;
}

// ---------------------------------------------------------------------------
// Fused preprocess: blocks [0, 8192) convert x -> fp16;
//                   blocks [8192, 16384) pack mask -> bits (warp ballot).
// ---------------------------------------------------------------------------
#define XBLOCKS 8192
__global__ __launch_bounds__(256) void convert_xm_kernel(
    const float* __restrict__ x, const float* __restrict__ m)
{
    int bid = blockIdx.x;
    if (bid < XBLOCKS) {
        int i = (bid * 256 + threadIdx.x) * 4;
        float4 v = *(const float4*)(x + i);
        *(uint32_t*)(g_x + i)     = pack_f16(__float2half_rn(v.x),
                                             __float2half_rn(v.y));
        *(uint32_t*)(g_x + i + 2) = pack_f16(__float2half_rn(v.z),
                                             __float2half_rn(v.w));
    } else {
        // each warp packs 128 consecutive mask floats -> 4 bit-words
        int gw = (bid - XBLOCKS) * 8 + (threadIdx.x >> 5);  // global warp id
        int lane = threadIdx.x & 31;
        size_t base = (size_t)gw * 128;
        uint32_t words[4];
        #pragma unroll
        for (int j = 0; j < 4; j++) {
            float v = m[base + j * 32 + lane];
            words[j] = __ballot_sync(0xffffffffu, v != 0.0f);
        }
        if (lane < 4)
            g_mb[(size_t)gw * 4 + lane] = words[lane];
    }
}

// Preprocess: W[k][n] -> Wt[n][k] fp16
__global__ __launch_bounds__(256) void convert_wt_kernel(
    const float* __restrict__ Wq, const float* __restrict__ Wk,
    const float* __restrict__ Wv)
{
    __shared__ float t[32][33];
    const int z = blockIdx.z;
    const float* __restrict__ W = (z == 0) ? Wq : (z == 1 ? Wk : Wv);
    const int n0 = blockIdx.x * 32, k0 = blockIdx.y * 32;
    const int tx = threadIdx.x, ty = threadIdx.y;   // block (32, 8)

    #pragma unroll
    for (int i = ty; i < 32; i += 8)
        t[i][tx] = W[(size_t)(k0 + i) * DIM + n0 + tx];
    __syncthreads();

    __half* wt = g_wt + (size_t)z * DIM * DIM;
    #pragma unroll
    for (int i = ty; i < 32; i += 8)
        wt[(size_t)(n0 + i) * DIM + k0 + tx] = __float2half_rn(t[tx][i]);
}

// ---------------------------------------------------------------------------
// QKV projection GEMM (R13 verbatim): plain fp16, 1 MMA per tile.
//   CTA tile 64x128, 8 warps (2x4), warp tile 32x32, BK=64, 4 CTAs/SM.
// ---------------------------------------------------------------------------
#define BK 64
#define LDS 72
#define QXREG (64 * LDS)
#define QWOFF (QXREG * 2)
#define QBUFB ((64 + 128) * LDS * 2)
#define QKV_SMEM (2 * QBUFB)

__device__ __forceinline__ void qkv_cp_blk(
    uint32_t dstb, const __half* sx, const __half* sw, int k0, int tid)
{
    const __half* x = sx + k0;
    #pragma unroll
    for (int i = tid; i < 512; i += 256) {
        int r = i >> 3, c8 = (i & 7) * 8;
        cp16(dstb + (r * LDS + c8) * 2, x + (size_t)r * DIM + c8);
    }
    const __half* wsrc = sw + k0;
    #pragma unroll
    for (int i = tid; i < 1024; i += 256) {
        int r = i >> 3, c8 = (i & 7) * 8;
        cp16(dstb + QWOFF + (r * LDS + c8) * 2, wsrc + (size_t)r * DIM + c8);
    }
}

__global__ __launch_bounds__(256, 4) void qkv_mma_kernel()
{
    extern __shared__ __half smd[];
    const uint32_t smb = smem_u32(smd);

    const int tid  = threadIdx.x;
    const int w    = tid >> 5, lane = tid & 31;
    const int wm   = w >> 2, wn = w & 3;
    const int m0   = blockIdx.x * 64;
    const int n0   = blockIdx.y * 128;
    const int z    = blockIdx.z;

    const __half* sx = g_x + (size_t)m0 * DIM;
    const __half* sw = g_wt + (size_t)z * DIM * DIM + (size_t)n0 * DIM;

    const int a_row = lane & 15, a_kh = (lane >> 4) * 8;
    const int b_row = (lane & 7) + ((lane >> 4) << 3);
    const int b_kh  = ((lane >> 3) & 1) * 8;

    float acc[2][4][4] = {};

    qkv_cp_blk(smb, sx, sw, 0, tid); CP_COMMIT();

    const int NB = DIM / BK;   // 16
    for (int blk = 0; blk < NB; blk++) {
        CP_WAIT(0);
        __syncthreads();
        if (blk + 1 < NB) {
            qkv_cp_blk(smb + ((blk + 1) & 1) * QBUFB, sx, sw,
                       (blk + 1) * BK, tid);
            CP_COMMIT();
        }

        const uint32_t bb = smb + (blk & 1) * QBUFB;
        #pragma unroll
        for (int kk = 0; kk < BK; kk += 16) {
            uint32_t ax[2][4];
            #pragma unroll
            for (int mt = 0; mt < 2; mt++) {
                int roff = ((wm * 32 + mt * 16 + a_row) * LDS + kk + a_kh) * 2;
                ldsm_x4(ax[mt], bb + roff);
            }
            uint32_t bw[2][4];
            #pragma unroll
            for (int p = 0; p < 2; p++) {
                int roff = ((wn * 32 + p * 16 + b_row) * LDS + kk + b_kh) * 2;
                ldsm_x4(bw[p], bb + QWOFF + roff);
            }
            #pragma unroll
            for (int mt = 0; mt < 2; mt++)
                #pragma unroll
                for (int p = 0; p < 2; p++) {
                    mma_f16(acc[mt][p * 2],     ax[mt], &bw[p][0]);
                    mma_f16(acc[mt][p * 2 + 1], ax[mt], &bw[p][2]);
                }
        }
    }

    // epilogue -> fp16 (q, k plain row-major; v^T plain)
    const int em = lane >> 2, en = (lane & 3) * 2;
    #pragma unroll
    for (int mt = 0; mt < 2; mt++) {
        #pragma unroll
        for (int nt = 0; nt < 4; nt++) {
            int mg0 = m0 + wm * 32 + mt * 16 + em;
            int ng  = n0 + wn * 32 + nt * 8 + en;
            int h = ng >> 6, hd = ng & 63;
            #pragma unroll
            for (int half_i = 0; half_i < 2; half_i++) {
                int mg = mg0 + half_i * 8;
                int b = mg >> 10, s = mg & 1023;
                int bhI = b * NH + h;
                float c0 = acc[mt][nt][half_i * 2 + 0];
                float c1 = acc[mt][nt][half_i * 2 + 1];
                __half h0 = __float2half_rn(c0);
                __half h1 = __float2half_rn(c1);
                if (z == 2) {
                    size_t base = ((size_t)bhI * HD + hd) * SEQ + s;
                    g_vt[base] = h0; g_vt[base + SEQ] = h1;
                } else {
                    size_t off = ((size_t)bhI * SEQ + s) * HD + hd;
                    *(uint32_t*)((z ? g_k : g_q) + off) = pack_f16(h0, h1);
                }
            }
        }
    }
}

// ---------------------------------------------------------------------------
// Attention (R14 bit-mask version + deg-4 poly + I2F-free bit extract).
//   smem: 2 buffers x { K, V [64][72] fp16 (18432 B) + mask bits 1 KB }.
//   Q (plain, 18432 B) staged in buffer 0 at startup, then recycled.
// ---------------------------------------------------------------------------
#define ATS 72
#define SM_K  (64 * ATS)             // 4608 elems per region
#define AMASK_OFF (2 * SM_K * 2)     // 18432: mask byte offset within buffer
#define ABUF_BYTES (AMASK_OFF + 1024)  // 19456
#define ATTN_SMEM (2 * ABUF_BYTES)   // 38912

__device__ __forceinline__ void attn_cp_tile(
    uint32_t dstb, const __half* K, const __half* V,
    const uint32_t* MB, int kt, int tid)
{
    #pragma unroll
    for (int i = tid; i < 512; i += 256) {
        int r = i >> 3, c8 = (i & 7) * 8;
        uint32_t d = dstb + (r * ATS + c8) * 2;
        cp16(d,            K + (size_t)(kt * 64 + r) * HD + c8);
        cp16(d + SM_K * 2, V + (size_t)r * SEQ + kt * 64 + c8);
    }
    // mask bits: 128 rows x 2 words (8 B per row)
    if (tid < 128)
        cp8(dstb + AMASK_OFF + tid * 8,
            MB + (size_t)tid * (SEQ / 32) + kt * 2);
}

__global__ __launch_bounds__(256, 2) void attn_mma_kernel(float* __restrict__ out)
{
    extern __shared__ __half smd[];
    const uint32_t smb = smem_u32(smd);
    const char* sb = (const char*)smd;

    const int tid = threadIdx.x, w = tid >> 5, lane = tid & 31;
    const int qt = blockIdx.x, bh = blockIdx.y;
    const int b = bh >> 4, h = bh & 15;
    const int gr = lane >> 2, gc2 = (lane & 3) * 2;

    const __half* Q  = g_q  + ((size_t)bh * SEQ + qt * 128) * HD;
    const __half* K  = g_k  + (size_t)bh * SEQ * HD;
    const __half* V  = g_vt + (size_t)bh * HD * SEQ;
    const uint32_t* MB = g_mb + (size_t)(b * SEQ + qt * 128) * (SEQ / 32);

    // ---- stage Q (plain) in buffer space, consume to registers ----
    #pragma unroll
    for (int i = tid; i < 1024; i += 256) {
        int r = i >> 3, c8 = (i & 7) * 8;
        cp16(smb + (r * ATS + c8) * 2, Q + (size_t)r * HD + c8);
    }
    CP_COMMIT();
    CP_WAIT(0);
    __syncthreads();

    uint32_t qf[4][4];
    {
        const int ar = w * 16 + (lane & 15);
        const int ac = ((lane >> 4) & 1) * 8;
        #pragma unroll
        for (int ks = 0; ks < 4; ks++)
            ldsm_x4(qf[ks], smb + (ar * ATS + ks * 16 + ac) * 2);
    }
    __syncthreads();   // all warps done reading Q before buffers are recycled

    attn_cp_tile(smb, K, V, MB, 0, tid); CP_COMMIT();

    float ctx[8][4] = {};
    float rs0 = 0.f, rs1 = 0.f;

    const int br = (lane & 7) + ((lane >> 4) << 3);
    const int bc = ((lane >> 3) & 1) * 8;
    const int mrow_off = (w * 16 + gr) * 8;   // bytes within mask region

    for (int kt = 0; kt < 16; kt++) {
        CP_WAIT(0);
        __syncthreads();
        if (kt + 1 < 16) {
            attn_cp_tile(smb + ((kt + 1) & 1) * ABUF_BYTES,
                         K, V, MB, kt + 1, tid);
            CP_COMMIT();
        }

        const uint32_t bb = smb + (kt & 1) * ABUF_BYTES;

        // ---- scores = Q K^T (plain: 1 MMA) ----
        float acc[8][4] = {};
        #pragma unroll
        for (int ks = 0; ks < 4; ks++) {
            #pragma unroll
            for (int ntp = 0; ntp < 4; ntp++) {
                uint32_t k4[4];
                int off = ((ntp * 16 + br) * ATS + ks * 16 + bc) * 2;
                ldsm_x4(k4, bb + off);
                mma_f16(acc[ntp * 2],     qf[ks], &k4[0]);
                mma_f16(acc[ntp * 2 + 1], qf[ks], &k4[2]);
            }
        }

        // ---- e = poly_exp(s/8) * mask-bit; sums; P frags ----
        const char* mp = sb + (kt & 1) * ABUF_BYTES + AMASK_OFF + mrow_off;
        uint2 mw0 = *(const uint2*)(mp);        // row gr+w*16, 64 bits
        uint2 mw1 = *(const uint2*)(mp + 64);   // row +8
        uint32_t ph[4][4];
        #pragma unroll
        for (int nt = 0; nt < 8; nt++) {
            int s = (nt & 3) * 8 + gc2;          // bit within 32-bit word
            uint32_t w0 = (nt < 4) ? mw0.x : mw0.y;
            uint32_t w1 = (nt < 4) ? mw1.x : mw1.y;
            float e0 = fexp8(acc[nt][0]) * bit_to_f(w0, s);
            float e1 = fexp8(acc[nt][1]) * bit_to_f(w0, s + 1);
            float e2 = fexp8(acc[nt][2]) * bit_to_f(w1, s);
            float e3 = fexp8(acc[nt][3]) * bit_to_f(w1, s + 1);
            rs0 += e0 + e1;
            rs1 += e2 + e3;
            int u = nt >> 1, sel = (nt & 1) * 2;
            ph[u][sel]     = cvt_f16x2(e0, e1);
            ph[u][sel + 1] = cvt_f16x2(e2, e3);
        }

        // ---- ctx += P V (plain: 1 MMA) ----
        #pragma unroll
        for (int u = 0; u < 4; u++) {
            #pragma unroll
            for (int dtp = 0; dtp < 4; dtp++) {
                uint32_t v4[4];
                int off = ((dtp * 16 + br) * ATS + u * 16 + bc) * 2;
                ldsm_x4(v4, bb + SM_K * 2 + off);
                mma_f16(ctx[dtp * 2],     ph[u], &v4[0]);
                mma_f16(ctx[dtp * 2 + 1], ph[u], &v4[2]);
            }
        }
    }

    // ---- denominators + output ----
    rs0 += __shfl_xor_sync(0xffffffffu, rs0, 1);
    rs0 += __shfl_xor_sync(0xffffffffu, rs0, 2);
    rs1 += __shfl_xor_sync(0xffffffffu, rs1, 1);
    rs1 += __shfl_xor_sync(0xffffffffu, rs1, 2);
    float inv0 = 1.0f / (rs0 + 1e-8f);
    float inv1 = 1.0f / (rs1 + 1e-8f);

    const int s0 = qt * 128 + w * 16 + gr;
    float* O = out + (((size_t)b * SEQ + s0) * NH + h) * HD + gc2;
    #pragma unroll
    for (int dt = 0; dt < 8; dt++) {
        *(float2*)&O[dt * 8] =
            make_float2(ctx[dt][0] * inv0, ctx[dt][1] * inv0);
        *(float2*)&O[(size_t)8 * NH * HD + dt * 8] =
            make_float2(ctx[dt][2] * inv1, ctx[dt][3] * inv1);
    }
}

// ---------------------------------------------------------------------------
extern "C" void kernel_launch(void* const* d_in, const int* in_sizes, int n_in,
                              void* d_out, int out_size)
{
    const float* x    = (const float*)d_in[0];
    const float* mask = (const float*)d_in[1];
    const float* Wq   = (const float*)d_in[2];
    const float* Wk   = (const float*)d_in[3];
    const float* Wv   = (const float*)d_in[4];
    float* out = (float*)d_out;

    static int init = 0;
    if (!init) {
        cudaFuncSetAttribute(qkv_mma_kernel,
            cudaFuncAttributeMaxDynamicSharedMemorySize, QKV_SMEM);
        cudaFuncSetAttribute(attn_mma_kernel,
            cudaFuncAttributeMaxDynamicSharedMemorySize, ATTN_SMEM);
        init = 1;
    }

    // x: 8192 blocks; mask bits: 8.4M floats / (8 warps * 128) = 8192 blocks
    convert_xm_kernel<<<XBLOCKS + 8192, 256>>>(x, mask);
    convert_wt_kernel<<<dim3(32, 32, 3), dim3(32, 8)>>>(Wq, Wk, Wv);
    qkv_mma_kernel<<<dim3(128, 8, 3), 256, QKV_SMEM>>>();
    attn_mma_kernel<<<dim3(8, 128), 256, ATTN_SMEM>>>(out);
}